// round 14
// baseline (speedup 1.0000x reference)
#include <cuda_runtime.h>
#include <cuda_fp16.h>
#include <cstdint>
#include <math.h>

#define HID    256
#define BATCH  16
#define TT     255
#define MROWS  4080          // TT*BATCH
#define MPAD   4096          // padded row count (no OOB predication in loads)
#define VOCAB  32000
#define G4     1024          // 4*HID
#define NCTA   128           // persistent LSTM CTAs (each owns 2 hidden units)

// ---------------- device scratch (static: no runtime allocation) ----------------
__device__ alignas(16) __half g_X[MPAD * HID];        // fp16 embedded inputs (padded)
__device__ alignas(16) __half g_Wih[G4 * HID];        // fp16 W_ih
__device__ alignas(16) __half g_Wlin[VOCAB * HID];    // fp16 W_lin
__device__ alignas(16) float  g_biasIH[G4];           // b_ih + b_hh
__device__ alignas(16) float  g_gx[(size_t)MROWS * G4]; // precomputed x-gates (fp32)
__device__ alignas(16) float  g_h[2][BATCH * HID];    // double-buffered recurrent h (fp32)
__device__ alignas(16) __half g_H[MPAD * HID];        // h history (fp16, padded)
__device__ alignas(128) unsigned g_flag2[NCTA * 32];  // per-CTA step flags, 128B apart

// ---------------- helpers ----------------
__device__ __forceinline__ unsigned long long pack2(float x, float y) {
    unsigned long long r;
    asm("mov.b64 %0, {%1,%2};" : "=l"(r) : "f"(x), "f"(y));
    return r;
}
__device__ __forceinline__ void ffma2(unsigned long long &d, unsigned long long a,
                                      unsigned long long b) {
    asm("fma.rn.f32x2 %0, %1, %2, %0;" : "+l"(d) : "l"(a), "l"(b));
}
__device__ __forceinline__ float f2lo(unsigned long long v) {
    float lo, hi;
    asm("mov.b64 {%0,%1}, %2;" : "=f"(lo), "=f"(hi) : "l"(v));
    return lo;
}
__device__ __forceinline__ float f2hi(unsigned long long v) {
    float lo, hi;
    asm("mov.b64 {%0,%1}, %2;" : "=f"(lo), "=f"(hi) : "l"(v));
    return hi;
}
__device__ __forceinline__ float sigf(float x) { return 1.0f / (1.0f + __expf(-x)); }

__device__ __forceinline__ void ldm_x4(uint32_t *r, uint32_t addr) {
    asm volatile("ldmatrix.sync.aligned.m8n8.x4.shared.b16 {%0,%1,%2,%3}, [%4];"
                 : "=r"(r[0]), "=r"(r[1]), "=r"(r[2]), "=r"(r[3])
                 : "r"(addr));
}
__device__ __forceinline__ void mma16816(float *c, const uint32_t *a, uint32_t b0,
                                         uint32_t b1) {
    asm volatile(
        "mma.sync.aligned.m16n8k16.row.col.f32.f16.f16.f32 "
        "{%0,%1,%2,%3}, {%4,%5,%6,%7}, {%8,%9}, {%0,%1,%2,%3};"
        : "+f"(c[0]), "+f"(c[1]), "+f"(c[2]), "+f"(c[3])
        : "r"(a[0]), "r"(a[1]), "r"(a[2]), "r"(a[3]), "r"(b0), "r"(b1));
}
__device__ __forceinline__ void cpa16(uint32_t dst, const void *src) {
    asm volatile("cp.async.cg.shared.global [%0], [%1], 16;" :: "r"(dst), "l"(src));
}

// ---------------- prep kernels ----------------
__global__ void init_kernel() {
    int i = blockIdx.x * blockDim.x + threadIdx.x;   // 8192 threads
    if (i < NCTA * 32) g_flag2[i] = 0u;
    if (i < 2 * BATCH * HID) (&g_h[0][0])[i] = 0.0f;
}

__global__ void convert_kernel(const float *__restrict__ W_ih,
                               const float *__restrict__ W_lin,
                               const float *__restrict__ b_ih,
                               const float *__restrict__ b_hh) {
    int tid = blockIdx.x * blockDim.x + threadIdx.x;
    int stride = gridDim.x * blockDim.x;
    for (int i = tid; i < VOCAB * HID / 4; i += stride) {
        float4 v = *reinterpret_cast<const float4 *>(W_lin + (size_t)i * 4);
        __half2 h0 = __floats2half2_rn(v.x, v.y);
        __half2 h1 = __floats2half2_rn(v.z, v.w);
        uint2 u;
        u.x = *reinterpret_cast<uint32_t *>(&h0);
        u.y = *reinterpret_cast<uint32_t *>(&h1);
        *reinterpret_cast<uint2 *>(g_Wlin + (size_t)i * 4) = u;
    }
    for (int i = tid; i < G4 * HID / 4; i += stride) {
        float4 v = *reinterpret_cast<const float4 *>(W_ih + (size_t)i * 4);
        __half2 h0 = __floats2half2_rn(v.x, v.y);
        __half2 h1 = __floats2half2_rn(v.z, v.w);
        uint2 u;
        u.x = *reinterpret_cast<uint32_t *>(&h0);
        u.y = *reinterpret_cast<uint32_t *>(&h1);
        *reinterpret_cast<uint2 *>(g_Wih + (size_t)i * 4) = u;
    }
    for (int i = tid; i < G4; i += stride) g_biasIH[i] = b_ih[i] + b_hh[i];
}

// one block per row m = t*16+b; 64 threads cover HID=256 as float4
__global__ void gather_kernel(const int *__restrict__ old_tok,
                              const float *__restrict__ emb) {
    int m = blockIdx.x;
    int t = m >> 4, b = m & 15;
    int token = old_tok[b * 256 + t];          // old is [16][256]
    int k = threadIdx.x << 2;
    float4 v = make_float4(0.f, 0.f, 0.f, 0.f);
    if (token != 0) v = *reinterpret_cast<const float4 *>(emb + (size_t)token * HID + k);
    __half2 h0 = __floats2half2_rn(v.x, v.y);
    __half2 h1 = __floats2half2_rn(v.z, v.w);
    uint2 u;
    u.x = *reinterpret_cast<uint32_t *>(&h0);
    u.y = *reinterpret_cast<uint32_t *>(&h1);
    *reinterpret_cast<uint2 *>(g_X + m * HID + k) = u;
}

// ---------------- gemm1: mma.sync 128x128, 2-stage (proven, 15us) ------------
__global__ __launch_bounds__(256, 2) void gemm1_kernel() {
    constexpr int ASTG = 128 * 40;
    extern __shared__ __half smem_dyn[];
    __half *sA = smem_dyn;
    __half *sB = smem_dyn + 2 * ASTG;
    const __half *A = g_X;
    const __half *B = g_Wih;
    const int tid = threadIdx.x, lane = tid & 31, warp = tid >> 5;
    const int m0 = blockIdx.y * 128, n0 = blockIdx.x * 128;
    const int wm = (warp >> 2) << 6, wn = (warp & 3) << 5;

    float acc[4][4][4];
#pragma unroll
    for (int a = 0; a < 4; a++)
#pragma unroll
        for (int b = 0; b < 4; b++)
#pragma unroll
            for (int c = 0; c < 4; c++) acc[a][b][c] = 0.f;

    uint32_t sAb = (uint32_t)__cvta_generic_to_shared(sA);
    uint32_t sBb = (uint32_t)__cvta_generic_to_shared(sB);

#pragma unroll
    for (int i = tid; i < 512; i += 256) {
        int row = i >> 2, seg = i & 3;
        uint32_t off = (uint32_t)(row * 40 + seg * 8) << 1;
        cpa16(sAb + off, A + (size_t)(m0 + row) * HID + seg * 8);
        cpa16(sBb + off, B + (size_t)(n0 + row) * HID + seg * 8);
    }
    asm volatile("cp.async.commit_group;" ::: "memory");

    for (int chunk = 0; chunk < 8; chunk++) {
        if (chunk + 1 < 8) {
            int k0 = (chunk + 1) * 32;
            uint32_t soff = (uint32_t)(((chunk + 1) & 1) * ASTG) << 1;
#pragma unroll
            for (int i = tid; i < 512; i += 256) {
                int row = i >> 2, seg = i & 3;
                uint32_t off = soff + ((uint32_t)(row * 40 + seg * 8) << 1);
                cpa16(sAb + off, A + (size_t)(m0 + row) * HID + k0 + seg * 8);
                cpa16(sBb + off, B + (size_t)(n0 + row) * HID + k0 + seg * 8);
            }
            asm volatile("cp.async.commit_group;" ::: "memory");
            asm volatile("cp.async.wait_group 1;" ::: "memory");
        } else {
            asm volatile("cp.async.wait_group 0;" ::: "memory");
        }
        __syncthreads();

        uint32_t stg = (uint32_t)((chunk & 1) * ASTG) << 1;
#pragma unroll
        for (int kk = 0; kk < 32; kk += 16) {
            uint32_t af[4][4], bf[2][4];
            int cc = kk + ((lane >> 4) << 3);
#pragma unroll
            for (int mt = 0; mt < 4; mt++) {
                int r = wm + mt * 16 + (lane & 15);
                ldm_x4(af[mt], sAb + stg + ((uint32_t)(r * 40 + cc) << 1));
            }
#pragma unroll
            for (int p = 0; p < 2; p++) {
                int r = wn + p * 16 + (lane & 15);
                ldm_x4(bf[p], sBb + stg + ((uint32_t)(r * 40 + cc) << 1));
            }
#pragma unroll
            for (int mt = 0; mt < 4; mt++)
#pragma unroll
                for (int nt = 0; nt < 4; nt++)
                    mma16816(acc[mt][nt], af[mt], bf[nt >> 1][nt & 1],
                             bf[nt >> 1][(nt & 1) + 2]);
        }
        __syncthreads();
    }

    const int g = lane >> 2, t2 = (lane & 3) << 1;
#pragma unroll
    for (int mt = 0; mt < 4; mt++) {
        int r = m0 + wm + mt * 16 + g;
#pragma unroll
        for (int nt = 0; nt < 4; nt++) {
            int n = n0 + wn + nt * 8 + t2;
            float2 bv = *reinterpret_cast<const float2 *>(g_biasIH + n);
            float2 v0 = make_float2(acc[mt][nt][0] + bv.x, acc[mt][nt][1] + bv.y);
            float2 v1 = make_float2(acc[mt][nt][2] + bv.x, acc[mt][nt][3] + bv.y);
            if (r < MROWS)
                *reinterpret_cast<float2 *>(g_gx + (size_t)r * G4 + n) = v0;
            if (r + 8 < MROWS)
                *reinterpret_cast<float2 *>(g_gx + (size_t)(r + 8) * G4 + n) = v1;
        }
    }
}

// ---------------- gemm2: mma.sync 128x256, 3-stage, 1 sync/chunk -------------
__global__ __launch_bounds__(256, 1) void gemm2_kernel(const float *__restrict__ b_lin,
                                                       float *__restrict__ out) {
    constexpr int ASTG = 128 * 40;       // halves per A stage
    constexpr int BSTG = 256 * 40;       // halves per B stage
    extern __shared__ __half smem_dyn[];
    __half *sA = smem_dyn;               // [3][ASTG]
    __half *sB = smem_dyn + 3 * ASTG;    // [3][BSTG]

    const int tid = threadIdx.x, lane = tid & 31, warp = tid >> 5;
    const int m0 = blockIdx.y * 128, n0 = blockIdx.x * 256;
    const int wm = (warp >> 2) << 6, wn = (warp & 3) << 6;

    float acc[4][8][4];
#pragma unroll
    for (int a = 0; a < 4; a++)
#pragma unroll
        for (int b = 0; b < 8; b++)
#pragma unroll
            for (int c = 0; c < 4; c++) acc[a][b][c] = 0.f;

    uint32_t sAb = (uint32_t)__cvta_generic_to_shared(sA);
    uint32_t sBb = (uint32_t)__cvta_generic_to_shared(sB);

    // stage loader: chunk -> stage slot
#define LOAD_STAGE(chunk, stg)                                                     \
    do {                                                                           \
        int k0 = (chunk) * 32;                                                     \
        uint32_t aoff = (uint32_t)((stg) * ASTG) << 1;                             \
        uint32_t boff = (uint32_t)((stg) * BSTG) << 1;                             \
        for (int i = tid; i < 512; i += 256) {                                     \
            int row = i >> 2, seg = i & 3;                                         \
            cpa16(sAb + aoff + ((uint32_t)(row * 40 + seg * 8) << 1),              \
                  g_H + (size_t)(m0 + row) * HID + k0 + seg * 8);                  \
        }                                                                          \
        for (int i = tid; i < 1024; i += 256) {                                    \
            int row = i >> 2, seg = i & 3;                                         \
            cpa16(sBb + boff + ((uint32_t)(row * 40 + seg * 8) << 1),              \
                  g_Wlin + (size_t)(n0 + row) * HID + k0 + seg * 8);               \
        }                                                                          \
        asm volatile("cp.async.commit_group;" ::: "memory");                       \
    } while (0)

    LOAD_STAGE(0, 0);
    LOAD_STAGE(1, 1);

    int stg = 0;
    for (int c = 0; c < 8; c++) {
        if (c < 7)
            asm volatile("cp.async.wait_group 1;" ::: "memory");
        else
            asm volatile("cp.async.wait_group 0;" ::: "memory");
        __syncthreads();   // chunk c visible; everyone past chunk c-1 mma

        if (c + 2 < 8) {
            int ns = stg + 2;
            if (ns >= 3) ns -= 3;
            LOAD_STAGE(c + 2, ns);
        }

        uint32_t stgA = (uint32_t)(stg * ASTG) << 1;
        uint32_t stgB = (uint32_t)(stg * BSTG) << 1;
#pragma unroll
        for (int kk = 0; kk < 32; kk += 16) {
            uint32_t af[4][4], bf[4][4];
            int cc = kk + ((lane >> 4) << 3);
#pragma unroll
            for (int mt = 0; mt < 4; mt++) {
                int r = wm + mt * 16 + (lane & 15);
                ldm_x4(af[mt], sAb + stgA + ((uint32_t)(r * 40 + cc) << 1));
            }
#pragma unroll
            for (int p = 0; p < 4; p++) {
                int r = wn + p * 16 + (lane & 15);
                ldm_x4(bf[p], sBb + stgB + ((uint32_t)(r * 40 + cc) << 1));
            }
#pragma unroll
            for (int mt = 0; mt < 4; mt++)
#pragma unroll
                for (int nt = 0; nt < 8; nt++)
                    mma16816(acc[mt][nt], af[mt], bf[nt >> 1][nt & 1],
                             bf[nt >> 1][(nt & 1) + 2]);
        }
        stg++;
        if (stg == 3) stg = 0;
    }
#undef LOAD_STAGE

    const int g = lane >> 2, t2 = (lane & 3) << 1;
#pragma unroll
    for (int mt = 0; mt < 4; mt++) {
        int r = m0 + wm + mt * 16 + g;
#pragma unroll
        for (int nt = 0; nt < 8; nt++) {
            int n = n0 + wn + nt * 8 + t2;
            float2 bv = *reinterpret_cast<const float2 *>(b_lin + n);
            float2 v0 = make_float2(acc[mt][nt][0] + bv.x, acc[mt][nt][1] + bv.y);
            float2 v1 = make_float2(acc[mt][nt][2] + bv.x, acc[mt][nt][3] + bv.y);
            if (r < MROWS) {
                int t = r >> 4, bb = r & 15;
                *reinterpret_cast<float2 *>(out + (size_t)(bb * TT + t) * VOCAB + n) = v0;
            }
            if (r + 8 < MROWS) {
                int t = (r + 8) >> 4, bb = (r + 8) & 15;
                *reinterpret_cast<float2 *>(out + (size_t)(bb * TT + t) * VOCAB + n) = v1;
            }
        }
    }
}

// ---------------- persistent LSTM recurrence ----------------
// 128 CTAs x 256 threads, CTA ci owns units u0=2ci..+1 (8 gate rows).
// Barrier: per-CTA flag words 128B apart (plain st.release, NO atomics);
// warp 0 of every CTA polls all 128 flags (32 lanes x 4 strided ld.acquire).
__global__ __launch_bounds__(256, 1) void lstm_kernel(const float *__restrict__ W_hh) {
    const int tid = threadIdx.x;
    const int b = tid >> 4, kc = tid & 15;
    const int u0 = blockIdx.x * 2;

    unsigned long long w2[8][8];
#pragma unroll
    for (int r = 0; r < 8; r++) {
        const float *wrow = W_hh + (size_t)((r >> 1) * HID + u0 + (r & 1)) * HID + kc * 16;
#pragma unroll
        for (int q = 0; q < 4; q++) {
            float4 v = *reinterpret_cast<const float4 *>(wrow + q * 4);
            w2[r][q * 2] = pack2(v.x, v.y);
            w2[r][q * 2 + 1] = pack2(v.z, v.w);
        }
    }
    float cst = 0.f;

    for (int s = 0; s < TT; s++) {
        float gxv[4];
        if (kc < 2) {
            const float *gp = g_gx + (size_t)(s * BATCH + b) * G4 + u0 + kc;
#pragma unroll
            for (int g = 0; g < 4; g++) gxv[g] = __ldcs(gp + g * HID);
        }
        if (s > 0) {
            if (tid < 32) {
                bool ok;
                do {
                    ok = true;
#pragma unroll
                    for (int j = 0; j < 4; j++) {
                        unsigned v;
                        asm volatile("ld.acquire.gpu.global.u32 %0, [%1];"
                                     : "=r"(v)
                                     : "l"(g_flag2 + (tid * 4 + j) * 32)
                                     : "memory");
                        ok &= (v >= (unsigned)s);
                    }
                } while (!__all_sync(0xffffffffu, ok));
            }
            __syncthreads();
        }
        const float *hp = g_h[s & 1] + b * HID + kc * 16;
        unsigned long long h2[8];
#pragma unroll
        for (int q = 0; q < 4; q++) {
            float4 v = __ldcg(reinterpret_cast<const float4 *>(hp + q * 4));
            h2[q * 2] = pack2(v.x, v.y);
            h2[q * 2 + 1] = pack2(v.z, v.w);
        }
        unsigned long long acc[8];
#pragma unroll
        for (int r = 0; r < 8; r++) acc[r] = pack2(0.f, 0.f);
#pragma unroll
        for (int q = 0; q < 8; q++)
#pragma unroll
            for (int r = 0; r < 8; r++) ffma2(acc[r], w2[r][q], h2[q]);

        float sred[8];
#pragma unroll
        for (int r = 0; r < 8; r++) sred[r] = f2lo(acc[r]) + f2hi(acc[r]);
#pragma unroll
        for (int m = 8; m >= 1; m >>= 1)
#pragma unroll
            for (int r = 0; r < 8; r++)
                sred[r] += __shfl_xor_sync(0xffffffffu, sred[r], m, 16);

        if (kc < 2) {
            float iv = sred[0 + kc] + gxv[0];
            float fv = sred[2 + kc] + gxv[1];
            float gv = sred[4 + kc] + gxv[2];
            float ov = sred[6 + kc] + gxv[3];
            cst = sigf(fv) * cst + sigf(iv) * tanhf(gv);
            float h = sigf(ov) * tanhf(cst);
            g_h[(s + 1) & 1][b * HID + u0 + kc] = h;
            g_H[(size_t)(s * BATCH + b) * HID + u0 + kc] = __float2half_rn(h);
        }
        __syncthreads();
        if (tid == 0)
            asm volatile("st.release.gpu.global.u32 [%0], %1;"
                         :: "l"(g_flag2 + blockIdx.x * 32), "r"((unsigned)(s + 1))
                         : "memory");
    }
}

// ---------------- launch ----------------
extern "C" void kernel_launch(void *const *d_in, const int *in_sizes, int n_in,
                              void *d_out, int out_size) {
    const int *old_tok = (const int *)d_in[0];
    const float *emb = (const float *)d_in[1];
    const float *W_ih = (const float *)d_in[2];
    const float *W_hh = (const float *)d_in[3];
    const float *b_ih = (const float *)d_in[4];
    const float *b_hh = (const float *)d_in[5];
    const float *W_lin = (const float *)d_in[6];
    const float *b_lin = (const float *)d_in[7];
    float *out = (float *)d_out;

    const int smem1 = (2 * 128 * 40 + 2 * 128 * 40) * 2;     // 40960 B
    const int smem2 = (3 * 128 * 40 + 3 * 256 * 40) * 2;     // 92160 B
    cudaFuncSetAttribute(gemm1_kernel, cudaFuncAttributeMaxDynamicSharedMemorySize, smem1);
    cudaFuncSetAttribute(gemm2_kernel, cudaFuncAttributeMaxDynamicSharedMemorySize, smem2);

    init_kernel<<<32, 256>>>();
    convert_kernel<<<2048, 256>>>(W_ih, W_lin, b_ih, b_hh);
    gather_kernel<<<MROWS, 64>>>(old_tok, emb);
    gemm1_kernel<<<dim3(G4 / 128, 32), 256, smem1>>>();
    lstm_kernel<<<NCTA, 256>>>(W_hh);
    gemm2_kernel<<<dim3(VOCAB / 256, MPAD / 128), 256, smem2>>>(b_lin, out);
}

// round 15
// speedup vs baseline: 1.3510x; 1.3510x over previous
#include <cuda_runtime.h>
#include <cuda_fp16.h>
#include <cstdint>
#include <math.h>

#define HID    256
#define BATCH  16
#define TT     255
#define MROWS  4080          // TT*BATCH
#define MPAD   4096          // padded row count (no OOB predication in loads)
#define VOCAB  32000
#define G4     1024          // 4*HID
#define NCTA   128           // persistent LSTM CTAs (each owns 2 hidden units)

// ---------------- device scratch (static: no runtime allocation) ----------------
__device__ alignas(16) __half g_X[MPAD * HID];        // fp16 embedded inputs (padded)
__device__ alignas(16) __half g_Wih[G4 * HID];        // fp16 W_ih
__device__ alignas(16) __half g_Wlin[VOCAB * HID];    // fp16 W_lin
__device__ alignas(16) float  g_biasIH[G4];           // b_ih + b_hh
__device__ alignas(16) float  g_gx[(size_t)MROWS * G4]; // precomputed x-gates (fp32)
__device__ alignas(16) float  g_h[2][BATCH * HID];    // double-buffered recurrent h (fp32)
__device__ alignas(16) __half g_H[MPAD * HID];        // h history (fp16, padded)
__device__ unsigned           g_cnt[256];             // per-step barrier counters

// ---------------- helpers ----------------
__device__ __forceinline__ unsigned long long pack2(float x, float y) {
    unsigned long long r;
    asm("mov.b64 %0, {%1,%2};" : "=l"(r) : "f"(x), "f"(y));
    return r;
}
__device__ __forceinline__ void ffma2(unsigned long long &d, unsigned long long a,
                                      unsigned long long b) {
    asm("fma.rn.f32x2 %0, %1, %2, %0;" : "+l"(d) : "l"(a), "l"(b));
}
__device__ __forceinline__ float f2lo(unsigned long long v) {
    float lo, hi;
    asm("mov.b64 {%0,%1}, %2;" : "=f"(lo), "=f"(hi) : "l"(v));
    return lo;
}
__device__ __forceinline__ float f2hi(unsigned long long v) {
    float lo, hi;
    asm("mov.b64 {%0,%1}, %2;" : "=f"(lo), "=f"(hi) : "l"(v));
    return hi;
}
__device__ __forceinline__ float sigf(float x) { return 1.0f / (1.0f + __expf(-x)); }

__device__ __forceinline__ void ldm_x4(uint32_t *r, uint32_t addr) {
    asm volatile("ldmatrix.sync.aligned.m8n8.x4.shared.b16 {%0,%1,%2,%3}, [%4];"
                 : "=r"(r[0]), "=r"(r[1]), "=r"(r[2]), "=r"(r[3])
                 : "r"(addr));
}
__device__ __forceinline__ void mma16816(float *c, const uint32_t *a, uint32_t b0,
                                         uint32_t b1) {
    asm volatile(
        "mma.sync.aligned.m16n8k16.row.col.f32.f16.f16.f32 "
        "{%0,%1,%2,%3}, {%4,%5,%6,%7}, {%8,%9}, {%0,%1,%2,%3};"
        : "+f"(c[0]), "+f"(c[1]), "+f"(c[2]), "+f"(c[3])
        : "r"(a[0]), "r"(a[1]), "r"(a[2]), "r"(a[3]), "r"(b0), "r"(b1));
}
__device__ __forceinline__ void cpa16(uint32_t dst, const void *src) {
    asm volatile("cp.async.cg.shared.global [%0], [%1], 16;" :: "r"(dst), "l"(src));
}

// ---------------- prep kernels ----------------
__global__ void init_kernel() {
    int i = blockIdx.x * blockDim.x + threadIdx.x;
    if (i < 256) g_cnt[i] = 0u;
    if (i < 2 * BATCH * HID) (&g_h[0][0])[i] = 0.0f;
}

__global__ void convert_kernel(const float *__restrict__ W_ih,
                               const float *__restrict__ W_lin,
                               const float *__restrict__ b_ih,
                               const float *__restrict__ b_hh) {
    int tid = blockIdx.x * blockDim.x + threadIdx.x;
    int stride = gridDim.x * blockDim.x;
    for (int i = tid; i < VOCAB * HID / 4; i += stride) {
        float4 v = *reinterpret_cast<const float4 *>(W_lin + (size_t)i * 4);
        __half2 h0 = __floats2half2_rn(v.x, v.y);
        __half2 h1 = __floats2half2_rn(v.z, v.w);
        uint2 u;
        u.x = *reinterpret_cast<uint32_t *>(&h0);
        u.y = *reinterpret_cast<uint32_t *>(&h1);
        *reinterpret_cast<uint2 *>(g_Wlin + (size_t)i * 4) = u;
    }
    for (int i = tid; i < G4 * HID / 4; i += stride) {
        float4 v = *reinterpret_cast<const float4 *>(W_ih + (size_t)i * 4);
        __half2 h0 = __floats2half2_rn(v.x, v.y);
        __half2 h1 = __floats2half2_rn(v.z, v.w);
        uint2 u;
        u.x = *reinterpret_cast<uint32_t *>(&h0);
        u.y = *reinterpret_cast<uint32_t *>(&h1);
        *reinterpret_cast<uint2 *>(g_Wih + (size_t)i * 4) = u;
    }
    for (int i = tid; i < G4; i += stride) g_biasIH[i] = b_ih[i] + b_hh[i];
}

// one block per row m = t*16+b; 64 threads cover HID=256 as float4
__global__ void gather_kernel(const int *__restrict__ old_tok,
                              const float *__restrict__ emb) {
    int m = blockIdx.x;
    int t = m >> 4, b = m & 15;
    int token = old_tok[b * 256 + t];          // old is [16][256]
    int k = threadIdx.x << 2;
    float4 v = make_float4(0.f, 0.f, 0.f, 0.f);
    if (token != 0) v = *reinterpret_cast<const float4 *>(emb + (size_t)token * HID + k);
    __half2 h0 = __floats2half2_rn(v.x, v.y);
    __half2 h1 = __floats2half2_rn(v.z, v.w);
    uint2 u;
    u.x = *reinterpret_cast<uint32_t *>(&h0);
    u.y = *reinterpret_cast<uint32_t *>(&h1);
    *reinterpret_cast<uint2 *>(g_X + m * HID + k) = u;
}

// ---------------- gemm1: mma.sync 128x128, 2-stage (proven, 15us) ------------
__global__ __launch_bounds__(256, 2) void gemm1_kernel() {
    constexpr int ASTG = 128 * 40;
    extern __shared__ __half smem_dyn[];
    __half *sA = smem_dyn;
    __half *sB = smem_dyn + 2 * ASTG;
    const __half *A = g_X;
    const __half *B = g_Wih;
    const int tid = threadIdx.x, lane = tid & 31, warp = tid >> 5;
    const int m0 = blockIdx.y * 128, n0 = blockIdx.x * 128;
    const int wm = (warp >> 2) << 6, wn = (warp & 3) << 5;

    float acc[4][4][4];
#pragma unroll
    for (int a = 0; a < 4; a++)
#pragma unroll
        for (int b = 0; b < 4; b++)
#pragma unroll
            for (int c = 0; c < 4; c++) acc[a][b][c] = 0.f;

    uint32_t sAb = (uint32_t)__cvta_generic_to_shared(sA);
    uint32_t sBb = (uint32_t)__cvta_generic_to_shared(sB);

#pragma unroll
    for (int i = tid; i < 512; i += 256) {
        int row = i >> 2, seg = i & 3;
        uint32_t off = (uint32_t)(row * 40 + seg * 8) << 1;
        cpa16(sAb + off, A + (size_t)(m0 + row) * HID + seg * 8);
        cpa16(sBb + off, B + (size_t)(n0 + row) * HID + seg * 8);
    }
    asm volatile("cp.async.commit_group;" ::: "memory");

    for (int chunk = 0; chunk < 8; chunk++) {
        if (chunk + 1 < 8) {
            int k0 = (chunk + 1) * 32;
            uint32_t soff = (uint32_t)(((chunk + 1) & 1) * ASTG) << 1;
#pragma unroll
            for (int i = tid; i < 512; i += 256) {
                int row = i >> 2, seg = i & 3;
                uint32_t off = soff + ((uint32_t)(row * 40 + seg * 8) << 1);
                cpa16(sAb + off, A + (size_t)(m0 + row) * HID + k0 + seg * 8);
                cpa16(sBb + off, B + (size_t)(n0 + row) * HID + k0 + seg * 8);
            }
            asm volatile("cp.async.commit_group;" ::: "memory");
            asm volatile("cp.async.wait_group 1;" ::: "memory");
        } else {
            asm volatile("cp.async.wait_group 0;" ::: "memory");
        }
        __syncthreads();

        uint32_t stg = (uint32_t)((chunk & 1) * ASTG) << 1;
#pragma unroll
        for (int kk = 0; kk < 32; kk += 16) {
            uint32_t af[4][4], bf[2][4];
            int cc = kk + ((lane >> 4) << 3);
#pragma unroll
            for (int mt = 0; mt < 4; mt++) {
                int r = wm + mt * 16 + (lane & 15);
                ldm_x4(af[mt], sAb + stg + ((uint32_t)(r * 40 + cc) << 1));
            }
#pragma unroll
            for (int p = 0; p < 2; p++) {
                int r = wn + p * 16 + (lane & 15);
                ldm_x4(bf[p], sBb + stg + ((uint32_t)(r * 40 + cc) << 1));
            }
#pragma unroll
            for (int mt = 0; mt < 4; mt++)
#pragma unroll
                for (int nt = 0; nt < 4; nt++)
                    mma16816(acc[mt][nt], af[mt], bf[nt >> 1][nt & 1],
                             bf[nt >> 1][(nt & 1) + 2]);
        }
        __syncthreads();
    }

    const int g = lane >> 2, t2 = (lane & 3) << 1;
#pragma unroll
    for (int mt = 0; mt < 4; mt++) {
        int r = m0 + wm + mt * 16 + g;
#pragma unroll
        for (int nt = 0; nt < 4; nt++) {
            int n = n0 + wn + nt * 8 + t2;
            float2 bv = *reinterpret_cast<const float2 *>(g_biasIH + n);
            float2 v0 = make_float2(acc[mt][nt][0] + bv.x, acc[mt][nt][1] + bv.y);
            float2 v1 = make_float2(acc[mt][nt][2] + bv.x, acc[mt][nt][3] + bv.y);
            if (r < MROWS)
                *reinterpret_cast<float2 *>(g_gx + (size_t)r * G4 + n) = v0;
            if (r + 8 < MROWS)
                *reinterpret_cast<float2 *>(g_gx + (size_t)(r + 8) * G4 + n) = v1;
        }
    }
}

// ---------------- gemm2: mma.sync 128x256, 3-stage, 1 sync/chunk -------------
__global__ __launch_bounds__(256, 1) void gemm2_kernel(const float *__restrict__ b_lin,
                                                       float *__restrict__ out) {
    constexpr int ASTG = 128 * 40;       // halves per A stage
    constexpr int BSTG = 256 * 40;       // halves per B stage
    extern __shared__ __half smem_dyn[];
    __half *sA = smem_dyn;               // [3][ASTG]
    __half *sB = smem_dyn + 3 * ASTG;    // [3][BSTG]

    const int tid = threadIdx.x, lane = tid & 31, warp = tid >> 5;
    const int m0 = blockIdx.y * 128, n0 = blockIdx.x * 256;
    const int wm = (warp >> 2) << 6, wn = (warp & 3) << 6;

    float acc[4][8][4];
#pragma unroll
    for (int a = 0; a < 4; a++)
#pragma unroll
        for (int b = 0; b < 8; b++)
#pragma unroll
            for (int c = 0; c < 4; c++) acc[a][b][c] = 0.f;

    uint32_t sAb = (uint32_t)__cvta_generic_to_shared(sA);
    uint32_t sBb = (uint32_t)__cvta_generic_to_shared(sB);

#define LOAD_STAGE(chunk, stg)                                                     \
    do {                                                                           \
        int k0 = (chunk) * 32;                                                     \
        uint32_t aoff = (uint32_t)((stg) * ASTG) << 1;                             \
        uint32_t boff = (uint32_t)((stg) * BSTG) << 1;                             \
        for (int i = tid; i < 512; i += 256) {                                     \
            int row = i >> 2, seg = i & 3;                                         \
            cpa16(sAb + aoff + ((uint32_t)(row * 40 + seg * 8) << 1),              \
                  g_H + (size_t)(m0 + row) * HID + k0 + seg * 8);                  \
        }                                                                          \
        for (int i = tid; i < 1024; i += 256) {                                    \
            int row = i >> 2, seg = i & 3;                                         \
            cpa16(sBb + boff + ((uint32_t)(row * 40 + seg * 8) << 1),              \
                  g_Wlin + (size_t)(n0 + row) * HID + k0 + seg * 8);               \
        }                                                                          \
        asm volatile("cp.async.commit_group;" ::: "memory");                       \
    } while (0)

    LOAD_STAGE(0, 0);
    LOAD_STAGE(1, 1);

    int stg = 0;
    for (int c = 0; c < 8; c++) {
        if (c < 7)
            asm volatile("cp.async.wait_group 1;" ::: "memory");
        else
            asm volatile("cp.async.wait_group 0;" ::: "memory");
        __syncthreads();

        if (c + 2 < 8) {
            int ns = stg + 2;
            if (ns >= 3) ns -= 3;
            LOAD_STAGE(c + 2, ns);
        }

        uint32_t stgA = (uint32_t)(stg * ASTG) << 1;
        uint32_t stgB = (uint32_t)(stg * BSTG) << 1;
#pragma unroll
        for (int kk = 0; kk < 32; kk += 16) {
            uint32_t af[4][4], bf[4][4];
            int cc = kk + ((lane >> 4) << 3);
#pragma unroll
            for (int mt = 0; mt < 4; mt++) {
                int r = wm + mt * 16 + (lane & 15);
                ldm_x4(af[mt], sAb + stgA + ((uint32_t)(r * 40 + cc) << 1));
            }
#pragma unroll
            for (int p = 0; p < 4; p++) {
                int r = wn + p * 16 + (lane & 15);
                ldm_x4(bf[p], sBb + stgB + ((uint32_t)(r * 40 + cc) << 1));
            }
#pragma unroll
            for (int mt = 0; mt < 4; mt++)
#pragma unroll
                for (int nt = 0; nt < 8; nt++)
                    mma16816(acc[mt][nt], af[mt], bf[nt >> 1][nt & 1],
                             bf[nt >> 1][(nt & 1) + 2]);
        }
        stg++;
        if (stg == 3) stg = 0;
    }
#undef LOAD_STAGE

    const int g = lane >> 2, t2 = (lane & 3) << 1;
#pragma unroll
    for (int mt = 0; mt < 4; mt++) {
        int r = m0 + wm + mt * 16 + g;
#pragma unroll
        for (int nt = 0; nt < 8; nt++) {
            int n = n0 + wn + nt * 8 + t2;
            float2 bv = *reinterpret_cast<const float2 *>(b_lin + n);
            float2 v0 = make_float2(acc[mt][nt][0] + bv.x, acc[mt][nt][1] + bv.y);
            float2 v1 = make_float2(acc[mt][nt][2] + bv.x, acc[mt][nt][3] + bv.y);
            if (r < MROWS) {
                int t = r >> 4, bb = r & 15;
                *reinterpret_cast<float2 *>(out + (size_t)(bb * TT + t) * VOCAB + n) = v0;
            }
            if (r + 8 < MROWS) {
                int t = (r + 8) >> 4, bb = (r + 8) & 15;
                *reinterpret_cast<float2 *>(out + (size_t)(bb * TT + t) * VOCAB + n) = v1;
            }
        }
    }
}

// ---------------- persistent LSTM recurrence (R10-proven barrier) ------------
// 128 CTAs x 256 threads, CTA ci owns units u0=2ci..+1 (8 gate rows).
// Barrier: single per-step counter; producer red.release, one acquire-poller/CTA.
__global__ __launch_bounds__(256, 1) void lstm_kernel(const float *__restrict__ W_hh) {
    const int tid = threadIdx.x;
    const int b = tid >> 4, kc = tid & 15;
    const int u0 = blockIdx.x * 2;

    unsigned long long w2[8][8];
#pragma unroll
    for (int r = 0; r < 8; r++) {
        const float *wrow = W_hh + (size_t)((r >> 1) * HID + u0 + (r & 1)) * HID + kc * 16;
#pragma unroll
        for (int q = 0; q < 4; q++) {
            float4 v = *reinterpret_cast<const float4 *>(wrow + q * 4);
            w2[r][q * 2] = pack2(v.x, v.y);
            w2[r][q * 2 + 1] = pack2(v.z, v.w);
        }
    }
    float cst = 0.f;

    for (int s = 0; s < TT; s++) {
        float gxv[4];
        if (kc < 2) {
            const float *gp = g_gx + (size_t)(s * BATCH + b) * G4 + u0 + kc;
#pragma unroll
            for (int g = 0; g < 4; g++) gxv[g] = __ldcs(gp + g * HID);
        }
        if (s > 0) {
            if (tid == 0) {
                unsigned v;
                do {
                    asm volatile("ld.acquire.gpu.global.u32 %0, [%1];"
                                 : "=r"(v) : "l"(g_cnt + (s - 1)) : "memory");
                } while (v < (unsigned)NCTA);
            }
            __syncthreads();
        }
        const float *hp = g_h[s & 1] + b * HID + kc * 16;
        unsigned long long h2[8];
#pragma unroll
        for (int q = 0; q < 4; q++) {
            float4 v = __ldcg(reinterpret_cast<const float4 *>(hp + q * 4));
            h2[q * 2] = pack2(v.x, v.y);
            h2[q * 2 + 1] = pack2(v.z, v.w);
        }
        unsigned long long acc[8];
#pragma unroll
        for (int r = 0; r < 8; r++) acc[r] = pack2(0.f, 0.f);
#pragma unroll
        for (int q = 0; q < 8; q++)
#pragma unroll
            for (int r = 0; r < 8; r++) ffma2(acc[r], w2[r][q], h2[q]);

        float sred[8];
#pragma unroll
        for (int r = 0; r < 8; r++) sred[r] = f2lo(acc[r]) + f2hi(acc[r]);
#pragma unroll
        for (int m = 8; m >= 1; m >>= 1)
#pragma unroll
            for (int r = 0; r < 8; r++)
                sred[r] += __shfl_xor_sync(0xffffffffu, sred[r], m, 16);

        if (kc < 2) {
            float iv = sred[0 + kc] + gxv[0];
            float fv = sred[2 + kc] + gxv[1];
            float gv = sred[4 + kc] + gxv[2];
            float ov = sred[6 + kc] + gxv[3];
            cst = sigf(fv) * cst + sigf(iv) * tanhf(gv);
            float h = sigf(ov) * tanhf(cst);
            g_h[(s + 1) & 1][b * HID + u0 + kc] = h;
            g_H[(size_t)(s * BATCH + b) * HID + u0 + kc] = __float2half_rn(h);
        }
        __syncthreads();
        if (tid == 0)
            asm volatile("red.release.gpu.global.add.u32 [%0], %1;"
                         :: "l"(g_cnt + s), "r"(1u) : "memory");
    }
}

// ---------------- launch ----------------
extern "C" void kernel_launch(void *const *d_in, const int *in_sizes, int n_in,
                              void *d_out, int out_size) {
    const int *old_tok = (const int *)d_in[0];
    const float *emb = (const float *)d_in[1];
    const float *W_ih = (const float *)d_in[2];
    const float *W_hh = (const float *)d_in[3];
    const float *b_ih = (const float *)d_in[4];
    const float *b_hh = (const float *)d_in[5];
    const float *W_lin = (const float *)d_in[6];
    const float *b_lin = (const float *)d_in[7];
    float *out = (float *)d_out;

    const int smem1 = (2 * 128 * 40 + 2 * 128 * 40) * 2;     // 40960 B
    const int smem2 = (3 * 128 * 40 + 3 * 256 * 40) * 2;     // 92160 B
    cudaFuncSetAttribute(gemm1_kernel, cudaFuncAttributeMaxDynamicSharedMemorySize, smem1);
    cudaFuncSetAttribute(gemm2_kernel, cudaFuncAttributeMaxDynamicSharedMemorySize, smem2);

    init_kernel<<<32, 256>>>();
    convert_kernel<<<2048, 256>>>(W_ih, W_lin, b_ih, b_hh);
    gather_kernel<<<MROWS, 64>>>(old_tok, emb);
    gemm1_kernel<<<dim3(G4 / 128, 32), 256, smem1>>>();
    lstm_kernel<<<NCTA, 256>>>(W_hh);
    gemm2_kernel<<<dim3(VOCAB / 256, MPAD / 128), 256, smem2>>>(b_lin, out);
}